// round 15
// baseline (speedup 1.0000x reference)
#include <cuda_runtime.h>
#include <cuda_bf16.h>
#include <math.h>

#define N_NODES 50000
#define N_EDGES 800000
#define HID 256
#define IN_CH 320

typedef unsigned long long u64;
typedef unsigned int u32;

// ---------------- static scratch (no runtime allocation) ----------------
__device__ float4 g_posfeat4 [N_NODES * 64 / 4];
__device__ float4 g_identity4[N_NODES * HID / 4];
__device__ float4 g_xl4      [N_NODES * HID / 4];
__device__ float4 g_xr4      [N_NODES * HID / 4];
__device__ float4 g_outpre4  [N_NODES * HID / 4];
__device__ float  g_norm_uv  [N_NODES * 2];
__device__ float4 g_logits4  [N_EDGES];
__device__ int    g_deg      [N_NODES];
__device__ int    g_cursor   [N_NODES];
__device__ int    g_rowstart [N_NODES];
__device__ int2   g_csr      [N_EDGES];
__device__ int    g_blocksums[256];
__device__ int    g_ei_is64;

__device__ __align__(16) __nv_bfloat16 g_Bhi [3 * 256 * IN_CH];
__device__ __align__(16) __nv_bfloat16 g_Blo [3 * 256 * IN_CH];
__device__ __align__(16) __nv_bfloat16 g_Bphi[256 * 256];
__device__ __align__(16) __nv_bfloat16 g_Bplo[256 * 256];

#define g_posfeat  ((float*)g_posfeat4)
#define g_identity ((float*)g_identity4)
#define g_xl       ((float*)g_xl4)
#define g_xr       ((float*)g_xr4)
#define g_outpre   ((float*)g_outpre4)
#define g_logits   ((float*)g_logits4)

// ---------------- PTX helpers ----------------
__device__ __forceinline__ u32 smem_u32(const void* p) {
    u32 a;
    asm("{ .reg .u64 t; cvta.to.shared.u64 t, %1; cvt.u32.u64 %0, t; }"
        : "=r"(a) : "l"(p));
    return a;
}
__device__ __forceinline__ void ldmx4(u32* r, u32 a) {
    asm volatile("ldmatrix.sync.aligned.m8n8.x4.shared.b16 {%0,%1,%2,%3}, [%4];"
                 : "=r"(r[0]), "=r"(r[1]), "=r"(r[2]), "=r"(r[3]) : "r"(a));
}
__device__ __forceinline__ void mma16816(float* d, const u32* a, const u32* b) {
    asm volatile("mma.sync.aligned.m16n8k16.row.col.f32.bf16.bf16.f32 "
                 "{%0,%1,%2,%3}, {%4,%5,%6,%7}, {%8,%9}, {%0,%1,%2,%3};"
                 : "+f"(d[0]), "+f"(d[1]), "+f"(d[2]), "+f"(d[3])
                 : "r"(a[0]), "r"(a[1]), "r"(a[2]), "r"(a[3]),
                   "r"(b[0]), "r"(b[1]));
}

// ---------------- kernel: detect edge_index dtype (1 warp, parallel) ----
__global__ void detect_kernel(const int* __restrict__ ei32) {
    int lane = threadIdx.x & 31;
    int bad = 0;
    #pragma unroll
    for (int j = 0; j < 8; j++)
        if (ei32[2 * (lane * 8 + j) + 1] != 0) bad = 1;
    u32 m = __ballot_sync(0xffffffffu, bad);
    if (lane == 0) g_ei_is64 = (m == 0);
}
__device__ __forceinline__ int load_idx(const void* ei, long long pos) {
    if (g_ei_is64) return (int)((const long long*)ei)[pos];
    return ((const int*)ei)[pos];
}

// ---------------- kernel: zero CSR counters ----------------
__global__ void zero_csr_kernel() {
    int i = blockIdx.x * blockDim.x + threadIdx.x;
    if (i < N_NODES) { g_deg[i] = 0; g_cursor[i] = 0; }
}

// ---------------- kernel: weight convert: split-bf16, [mat][n][k] -------
__global__ void bconv_kernel(const float* __restrict__ Wres,
                             const float* __restrict__ Wl,
                             const float* __restrict__ Wr,
                             const float* __restrict__ Wp) {
    int i = blockIdx.x * blockDim.x + threadIdx.x;
    if (i < 3 * 256 * IN_CH) {
        int mat = i / (256 * IN_CH);
        int rem = i % (256 * IN_CH);
        int n = rem / IN_CH, k = rem % IN_CH;
        const float* W = (mat == 0) ? Wres : (mat == 1) ? Wl : Wr;
        float w = W[k * 256 + n];
        __nv_bfloat16 h = __float2bfloat16(w);
        g_Bhi[i] = h;
        g_Blo[i] = __float2bfloat16(w - __bfloat162float(h));
    }
    if (i < 256 * 256) {
        int n = i >> 8, k = i & 255;
        float w = Wp[k * 256 + n];
        __nv_bfloat16 h = __float2bfloat16(w);
        g_Bphi[i] = h;
        g_Bplo[i] = __float2bfloat16(w - __bfloat162float(h));
    }
}

// ---------------- kernel: node prep (norm_uv, pos-MLP) ----------------
__global__ void node_prep_kernel(const float* __restrict__ kpts,
                                 const float* __restrict__ pts3d,
                                 const float* __restrict__ W1,
                                 const float* __restrict__ b1,
                                 const float* __restrict__ W2,
                                 const float* __restrict__ b2) {
    __shared__ float sW1[96], sb1[32], sW2[2048], sb2[64];
    int t = threadIdx.x;
    for (int i = t; i < 96;   i += blockDim.x) sW1[i] = W1[i];
    for (int i = t; i < 32;   i += blockDim.x) sb1[i] = b1[i];
    for (int i = t; i < 2048; i += blockDim.x) sW2[i] = W2[i];
    for (int i = t; i < 64;   i += blockDim.x) sb2[i] = b2[i];
    __syncthreads();

    int tid = blockIdx.x * blockDim.x + t;
    int nth = gridDim.x * blockDim.x;

    for (int n = tid; n < N_NODES; n += nth) {
        float u   = kpts[n * 2]     / 1216.0f;
        float v   = kpts[n * 2 + 1] / 352.0f;
        float dep = pts3d[n * 3 + 2];
        g_norm_uv[n * 2]     = u;
        g_norm_uv[n * 2 + 1] = v;
        float h[32];
        #pragma unroll
        for (int j = 0; j < 32; j++) {
            float z = u * sW1[j] + v * sW1[32 + j] + dep * sW1[64 + j] + sb1[j];
            h[j] = z / (1.0f + __expf(-z));
        }
        float4* dst = (float4*)(g_posfeat + n * 64);
        #pragma unroll
        for (int j4 = 0; j4 < 16; j4++) {
            float o0 = sb2[j4 * 4 + 0], o1 = sb2[j4 * 4 + 1];
            float o2 = sb2[j4 * 4 + 2], o3 = sb2[j4 * 4 + 3];
            #pragma unroll
            for (int k = 0; k < 32; k++) {
                float hk = h[k];
                const float* w = sW2 + k * 64 + j4 * 4;
                o0 += hk * w[0]; o1 += hk * w[1];
                o2 += hk * w[2]; o3 += hk * w[3];
            }
            dst[j4] = make_float4(o0, o1, o2, o3);
        }
    }
}

// ---------------- kernels: CSR build (by dst) ----------------
__global__ void deg_kernel(const void* __restrict__ ei) {
    int e = blockIdx.x * blockDim.x + threadIdx.x;
    if (e >= N_EDGES) return;
    int d = load_idx(ei, (long long)N_EDGES + e);
    if (d >= 0 && d < N_NODES) atomicAdd(&g_deg[d], 1);
}

__global__ void scan_blocks_kernel() {
    int t = threadIdx.x, lane = t & 31, w = t >> 5;
    int i = blockIdx.x * 256 + t;
    int v = (i < N_NODES) ? g_deg[i] : 0;
    int x = v;
    #pragma unroll
    for (int off = 1; off < 32; off <<= 1) {
        int y = __shfl_up_sync(0xffffffffu, x, off);
        if (lane >= off) x += y;
    }
    __shared__ int wsum[8];
    if (lane == 31) wsum[w] = x;
    __syncthreads();
    if (w == 0) {
        int s = (lane < 8) ? wsum[lane] : 0;
        #pragma unroll
        for (int off = 1; off < 8; off <<= 1) {
            int y = __shfl_up_sync(0xffffffffu, s, off);
            if (lane >= off) s += y;
        }
        if (lane < 8) wsum[lane] = s;
    }
    __syncthreads();
    int incl = x + ((w > 0) ? wsum[w - 1] : 0);
    if (i < N_NODES) g_rowstart[i] = incl - v;
    if (t == 255) g_blocksums[blockIdx.x] = incl;
}

__global__ void scan_sums_kernel(int nblocks) {
    int t = threadIdx.x, lane = t & 31, w = t >> 5;
    int v = (t < nblocks) ? g_blocksums[t] : 0;
    int x = v;
    #pragma unroll
    for (int off = 1; off < 32; off <<= 1) {
        int y = __shfl_up_sync(0xffffffffu, x, off);
        if (lane >= off) x += y;
    }
    __shared__ int wsum[8];
    if (lane == 31) wsum[w] = x;
    __syncthreads();
    if (w == 0) {
        int s = (lane < 8) ? wsum[lane] : 0;
        #pragma unroll
        for (int off = 1; off < 8; off <<= 1) {
            int y = __shfl_up_sync(0xffffffffu, s, off);
            if (lane >= off) s += y;
        }
        if (lane < 8) wsum[lane] = s;
    }
    __syncthreads();
    int incl = x + ((w > 0) ? wsum[w - 1] : 0);
    g_blocksums[t] = incl - v;
}

__global__ void scan_add_kernel() {
    int i = blockIdx.x * 256 + threadIdx.x;
    if (i < N_NODES) g_rowstart[i] += g_blocksums[blockIdx.x];
}

__global__ void fill_kernel(const void* __restrict__ ei) {
    int e = blockIdx.x * blockDim.x + threadIdx.x;
    if (e >= N_EDGES) return;
    int d = load_idx(ei, (long long)N_EDGES + e);
    int s = load_idx(ei, e);
    if (d < 0 || d >= N_NODES) return;
    if (s < 0) s = 0; if (s >= N_NODES) s = N_NODES - 1;
    int p = atomicAdd(&g_cursor[d], 1);
    int idx = g_rowstart[d] + p;
    if (idx >= 0 && idx < N_EDGES) g_csr[idx] = make_int2(e, s);
}

// ---------------- split-bf16 3-pass HMMA GEMM, 128x256 tile -------------
// SMEM per buffer (36864B): Ahi@0(6144), Alo@6144, Bhi@12288(12288), Blo@24576.
// Rows padded to 48B. 8 warps: wm=wid>>1 (M 32-rows), wn=wid&1 (N 128-cols).
template <int K>
__device__ __forceinline__ void mma_gemm_body(
    const float* __restrict__ A0, const float* __restrict__ A1,
    const __nv_bfloat16* __restrict__ Bh, const __nv_bfloat16* __restrict__ Bl,
    const float* __restrict__ bias, float* __restrict__ C, int bm)
{
    constexpr int NCHUNK = K / 16;
    constexpr int BUF = 36864;
    extern __shared__ char smem[];
    u32 sb = smem_u32(smem);
    int t = threadIdx.x, lane = t & 31, wid = t >> 5;
    int wm = wid >> 1, wn = wid & 1;

    int arow = t >> 1;               // A loader: 128 rows x 2 k-halves
    int ak   = t & 1;
    int gr   = bm + arow;
    bool rok = gr < N_NODES;
    u32 a_st = (u32)arow * 48 + (u32)ak * 16;
    int brow = t;                    // B loader: 256 rows, 1 thread each
    u32 b_st = (u32)brow * 48;

    float acc[2][16][4];
    #pragma unroll
    for (int i = 0; i < 2; i++)
        #pragma unroll
        for (int j = 0; j < 16; j++)
            #pragma unroll
            for (int q = 0; q < 4; q++) acc[i][j][q] = 0.0f;

    float v[8];
    uint4 bh0, bh1, bl0, bl1;

    auto ldg = [&](int kc) {
        int k0 = kc * 16;
        const float* p;
        if (K == 320 && k0 >= 256)
            p = A1 + (size_t)gr * 64 + (k0 - 256) + ak * 8;
        else
            p = A0 + (size_t)gr * 256 + k0 + ak * 8;
        if (rok) {
            float4 q0 = *(const float4*)p;
            float4 q1 = *(const float4*)(p + 4);
            v[0]=q0.x; v[1]=q0.y; v[2]=q0.z; v[3]=q0.w;
            v[4]=q1.x; v[5]=q1.y; v[6]=q1.z; v[7]=q1.w;
        } else {
            #pragma unroll
            for (int i = 0; i < 8; i++) v[i] = 0.0f;
        }
        size_t be = (size_t)brow * K + k0;
        bh0 = *(const uint4*)(Bh + be);
        bh1 = *(const uint4*)(Bh + be + 8);
        bl0 = *(const uint4*)(Bl + be);
        bl1 = *(const uint4*)(Bl + be + 8);
    };
    auto stsm = [&](int rb) {
        u32 h[4], l[4];
        #pragma unroll
        for (int j = 0; j < 4; j++) {
            __nv_bfloat162 hb = __floats2bfloat162_rn(v[2*j], v[2*j+1]);
            u32 hu = *(u32*)&hb;
            float f0 = __uint_as_float(hu << 16);
            float f1 = __uint_as_float(hu & 0xffff0000u);
            __nv_bfloat162 lb = __floats2bfloat162_rn(v[2*j] - f0, v[2*j+1] - f1);
            h[j] = hu; l[j] = *(u32*)&lb;
        }
        *(uint4*)(smem + rb +     0 + a_st) = make_uint4(h[0], h[1], h[2], h[3]);
        *(uint4*)(smem + rb +  6144 + a_st) = make_uint4(l[0], l[1], l[2], l[3]);
        *(uint4*)(smem + rb + 12288 + b_st) = bh0;
        *(uint4*)(smem + rb + 12288 + b_st + 16) = bh1;
        *(uint4*)(smem + rb + 24576 + b_st) = bl0;
        *(uint4*)(smem + rb + 24576 + b_st + 16) = bl1;
    };
    auto compute = [&](int rb) {
        u32 base = sb + rb;
        u32 ahi[2][4], alo[2][4];
        #pragma unroll
        for (int mi = 0; mi < 2; mi++) {
            u32 ra = base + (u32)(wm * 32 + mi * 16 + (lane & 15)) * 48
                          + (u32)(lane >> 4) * 16;
            ldmx4(ahi[mi], ra);
            ldmx4(alo[mi], ra + 6144);
        }
        #pragma unroll
        for (int np = 0; np < 8; np++) {
            int g  = lane >> 3;
            int nn = wn * 128 + np * 16 + ((g & 2) ? 8 : 0) + (lane & 7);
            u32 rb2 = base + 12288 + (u32)nn * 48 + (u32)(g & 1) * 16;
            u32 bh[4], bl2[4];
            ldmx4(bh, rb2);
            ldmx4(bl2, rb2 + 12288);
            #pragma unroll
            for (int mi = 0; mi < 2; mi++) {
                mma16816(acc[mi][np*2+0], ahi[mi], bh);
                mma16816(acc[mi][np*2+0], ahi[mi], bl2);
                mma16816(acc[mi][np*2+0], alo[mi], bh);
                mma16816(acc[mi][np*2+1], ahi[mi], bh + 2);
                mma16816(acc[mi][np*2+1], ahi[mi], bl2 + 2);
                mma16816(acc[mi][np*2+1], alo[mi], bh + 2);
            }
        }
    };

    ldg(0);
    stsm(0);
    __syncthreads();
    int buf = 0;
    for (int kc = 0; kc < NCHUNK; kc++) {
        bool more = (kc + 1) < NCHUNK;
        if (more) ldg(kc + 1);
        compute(buf * BUF);
        if (more) stsm((buf ^ 1) * BUF);
        __syncthreads();
        buf ^= 1;
    }

    #pragma unroll
    for (int mi = 0; mi < 2; mi++) {
        int row = bm + wm * 32 + mi * 16 + (lane >> 2);
        #pragma unroll
        for (int nj = 0; nj < 16; nj++) {
            int col = wn * 128 + nj * 8 + 2 * (lane & 3);
            float b0 = bias[col], b1 = bias[col + 1];
            if (row < N_NODES)
                *(float2*)(C + (size_t)row * 256 + col) =
                    make_float2(acc[mi][nj][0] + b0, acc[mi][nj][1] + b1);
            if (row + 8 < N_NODES)
                *(float2*)(C + (size_t)(row + 8) * 256 + col) =
                    make_float2(acc[mi][nj][2] + b0, acc[mi][nj][3] + b1);
        }
    }
}

__global__ void __launch_bounds__(256)
mma_nodes_kernel(const float* __restrict__ x,
                 const float* __restrict__ bres,
                 const float* __restrict__ bl,
                 const float* __restrict__ br) {
    int mat = blockIdx.y;
    const __nv_bfloat16* Bh = g_Bhi + (size_t)mat * 256 * IN_CH;
    const __nv_bfloat16* Bl = g_Blo + (size_t)mat * 256 * IN_CH;
    const float* bias = (mat == 0) ? bres : (mat == 1) ? bl : br;
    float* C          = (mat == 0) ? g_identity : (mat == 1) ? g_xl : g_xr;
    mma_gemm_body<IN_CH>(x, g_posfeat, Bh, Bl, bias, C, blockIdx.x * 128);
}

__global__ void __launch_bounds__(256)
mma_final_kernel(const float* __restrict__ bp, float* __restrict__ out) {
    mma_gemm_body<HID>(g_outpre, nullptr, g_Bphi, g_Bplo, bp, out,
                       blockIdx.x * 128);
}

// ---------------- attention: warp/node, depth-4 cp.async pipeline -------
__global__ void __launch_bounds__(256)
attn_kernel(const float* __restrict__ We,
            const float* __restrict__ att,
            const float* __restrict__ conv_bias,
            const float* __restrict__ gamma,
            const float* __restrict__ beta,
            float* __restrict__ out_final,
            int write_alpha) {
    __shared__ float sWe[768], sAtt[256], sCB[256], sG[256], sB[256];
    __shared__ __align__(16) float xlbuf[8][4][256];   // [warp][slot][ch]
    int t = threadIdx.x;
    for (int i = t; i < 768; i += 256) sWe[i] = We[i];
    sAtt[t] = att[t]; sCB[t] = conv_bias[t]; sG[t] = gamma[t]; sB[t] = beta[t];
    __syncthreads();

    int warp = t >> 5, lane = t & 31;
    int d = blockIdx.x * 8 + warp;
    if (d >= N_NODES) return;

    int c0 = lane * 8;
    int h  = lane >> 3;

    float xr[8], we0[8], we1[8], we2[8], ar[8];
    {
        const float4* p = (const float4*)(g_xr + (size_t)d * 256 + c0);
        float4 a = p[0], b = p[1];
        xr[0]=a.x; xr[1]=a.y; xr[2]=a.z; xr[3]=a.w;
        xr[4]=b.x; xr[5]=b.y; xr[6]=b.z; xr[7]=b.w;
    }
    #pragma unroll
    for (int i = 0; i < 8; i++) {
        we0[i] = sWe[c0 + i];
        we1[i] = sWe[256 + c0 + i];
        we2[i] = sWe[512 + c0 + i];
        ar[i]  = sAtt[c0 + i];
    }
    float uvd0 = g_norm_uv[d * 2], uvd1 = g_norm_uv[d * 2 + 1];
    int start = g_rowstart[d];
    int end   = start + g_deg[d];

    // cp.async dst: consecutive 16B per lane (4 lines per instr, minimal wf)
    u32 slot0 = smem_u32(&xlbuf[warp][0][0]);

    float lm = -INFINITY, dn = 0.f;
    float acc[8] = {0,0,0,0,0,0,0,0};

    auto issue = [&](int q, int2& cj, float2& uvj, int slot) {
        if (q < end) {
            cj  = g_csr[q];
            uvj = *(const float2*)(g_norm_uv + (size_t)cj.y * 2);
            const float* sp = g_xl + (size_t)cj.y * 256;
            u32 dp = slot0 + (u32)slot * 1024 + (u32)lane * 16;
            asm volatile(
                "cp.async.cg.shared.global [%0], [%2], 16;\n\t"
                "cp.async.cg.shared.global [%1], [%3], 16;"
                :: "r"(dp), "r"(dp + 512),
                   "l"(sp + lane * 4), "l"(sp + 128 + lane * 4) : "memory");
        }
        asm volatile("cp.async.commit_group;" ::: "memory");
    };

    auto compute = [&](int2 cj, float2 uvj, int slot) {
        asm volatile("cp.async.wait_group 3;" ::: "memory");
        __syncwarp();
        const float* bp_ = &xlbuf[warp][slot][c0];
        float4 ca = *(const float4*)bp_;
        float4 cb = *(const float4*)(bp_ + 4);
        float r0 = uvd0 - uvj.x;
        float r1 = uvd1 - uvj.y;
        float dist = sqrtf(r0 * r0 + r1 * r1);
        float xl[8] = {ca.x, ca.y, ca.z, ca.w, cb.x, cb.y, cb.z, cb.w};
        float part = 0.f;
        #pragma unroll
        for (int i = 0; i < 8; i++) {
            float m = xl[i] + xr[i] + r0 * we0[i] + r1 * we1[i] + dist * we2[i];
            m = (m >= 0.f) ? m : 0.2f * m;
            part += m * ar[i];
        }
        part += __shfl_xor_sync(0xffffffffu, part, 1);
        part += __shfl_xor_sync(0xffffffffu, part, 2);
        part += __shfl_xor_sync(0xffffffffu, part, 4);
        if ((lane & 7) == 0) g_logits[(size_t)cj.x * 4 + h] = part;

        float nm = fmaxf(lm, part);
        float sc = __expf(lm - nm);
        float ex = __expf(part - nm);
        dn = dn * sc + ex;
        #pragma unroll
        for (int i = 0; i < 8; i++) acc[i] = acc[i] * sc + ex * xl[i];
        lm = nm;
    };

    int2 e0, e1, e2, e3;
    float2 u0, u1, u2, u3;
    issue(start + 0, e0, u0, 0);
    issue(start + 1, e1, u1, 1);
    issue(start + 2, e2, u2, 2);
    issue(start + 3, e3, u3, 3);

    for (int p0 = start; p0 < end; p0 += 4) {
        if (p0 + 0 < end) { compute(e0, u0, 0); issue(p0 + 4, e0, u0, 0); }
        if (p0 + 1 < end) { compute(e1, u1, 1); issue(p0 + 5, e1, u1, 1); }
        if (p0 + 2 < end) { compute(e2, u2, 2); issue(p0 + 6, e2, u2, 2); }
        if (p0 + 3 < end) { compute(e3, u3, 3); issue(p0 + 7, e3, u3, 3); }
    }
    asm volatile("cp.async.wait_group 0;" ::: "memory");

    float dnT = dn + 1e-16f;

    if (write_alpha) {
        __threadfence_block();
        __syncwarp();
        float lmv[4], dnv[4];
        #pragma unroll
        for (int hh = 0; hh < 4; hh++) {
            lmv[hh] = __shfl_sync(0xffffffffu, lm,  hh * 8);
            dnv[hh] = __shfl_sync(0xffffffffu, dnT, hh * 8);
        }
        float* alpha_out = out_final + (size_t)N_NODES * 256;
        for (int q = start + lane; q < end; q += 32) {
            int eid = g_csr[q].x;
            float4 lg = g_logits4[eid];
            float4 al = make_float4(__expf(lg.x - lmv[0]) / dnv[0],
                                    __expf(lg.y - lmv[1]) / dnv[1],
                                    __expf(lg.z - lmv[2]) / dnv[2],
                                    __expf(lg.w - lmv[3]) / dnv[3]);
            *(float4*)(alpha_out + (size_t)eid * 4) = al;
        }
    }

    float o[8], s1 = 0.f, s2 = 0.f;
    float rdn = 1.0f / dnT;
    #pragma unroll
    for (int i = 0; i < 8; i++) {
        o[i] = acc[i] * rdn + sCB[c0 + i];
        s1 += o[i];
        s2 += o[i] * o[i];
    }
    #pragma unroll
    for (int off = 16; off >= 1; off >>= 1) {
        s1 += __shfl_xor_sync(0xffffffffu, s1, off);
        s2 += __shfl_xor_sync(0xffffffffu, s2, off);
    }
    float mean = s1 * (1.0f / 256.0f);
    float var  = s2 * (1.0f / 256.0f) - mean * mean;
    float rstd = rsqrtf(var + 1e-5f);

    const float4* ip = (const float4*)(g_identity + (size_t)d * 256 + c0);
    float4 ia = ip[0], ib = ip[1];
    float idn[8] = {ia.x, ia.y, ia.z, ia.w, ib.x, ib.y, ib.z, ib.w};

    float res[8];
    #pragma unroll
    for (int i = 0; i < 8; i++) {
        float y = (o[i] - mean) * rstd * sG[c0 + i] + sB[c0 + i];
        y = y / (1.0f + __expf(-y));
        res[i] = y + idn[i];
    }
    float4* op = (float4*)(g_outpre + (size_t)d * 256 + c0);
    op[0] = make_float4(res[0], res[1], res[2], res[3]);
    op[1] = make_float4(res[4], res[5], res[6], res[7]);
}

// ---------------- launch ----------------
extern "C" void kernel_launch(void* const* d_in, const int* in_sizes, int n_in,
                              void* d_out, int out_size) {
    const float* x    = (const float*)d_in[0];
    const float* kpts = (const float*)d_in[1];
    const float* p3d  = (const float*)d_in[2];
    const void*  ei   = d_in[3];
    const float* W1   = (const float*)d_in[4];
    const float* b1   = (const float*)d_in[5];
    const float* W2   = (const float*)d_in[6];
    const float* b2   = (const float*)d_in[7];
    const float* Wres = (const float*)d_in[8];
    const float* bres = (const float*)d_in[9];
    const float* Wl   = (const float*)d_in[10];
    const float* bl   = (const float*)d_in[11];
    const float* Wr   = (const float*)d_in[12];
    const float* br   = (const float*)d_in[13];
    const float* We   = (const float*)d_in[14];
    const float* att  = (const float*)d_in[15];
    const float* cb   = (const float*)d_in[16];
    const float* gam  = (const float*)d_in[17];
    const float* bet  = (const float*)d_in[18];
    const float* Wp   = (const float*)d_in[19];
    const float* bp   = (const float*)d_in[20];
    float* out = (float*)d_out;

    long long need = (long long)N_NODES * 256 + (long long)N_EDGES * 4;
    int write_alpha = ((long long)out_size >= need) ? 1 : 0;

    const int SMEM = 2 * 36864;   // 72KB double-buffered (128x256 tile)
    cudaFuncSetAttribute(mma_nodes_kernel,
                         cudaFuncAttributeMaxDynamicSharedMemorySize, SMEM);
    cudaFuncSetAttribute(mma_final_kernel,
                         cudaFuncAttributeMaxDynamicSharedMemorySize, SMEM);

    int mtiles = (N_NODES + 127) / 128;   // 391
    int nblk   = (N_NODES + 255) / 256;   // 196

    detect_kernel<<<1, 32>>>((const int*)ei);
    bconv_kernel<<<(3 * 256 * IN_CH + 255) / 256, 256>>>(Wres, Wl, Wr, Wp);
    node_prep_kernel<<<256, 256>>>(kpts, p3d, W1, b1, W2, b2);

    dim3 g1(mtiles, 3);
    mma_nodes_kernel<<<g1, 256, SMEM>>>(x, bres, bl, br);

    zero_csr_kernel<<<nblk, 256>>>();
    deg_kernel<<<(N_EDGES + 255) / 256, 256>>>(ei);
    scan_blocks_kernel<<<nblk, 256>>>();
    scan_sums_kernel<<<1, 256>>>(nblk);
    scan_add_kernel<<<nblk, 256>>>();
    fill_kernel<<<(N_EDGES + 255) / 256, 256>>>(ei);

    attn_kernel<<<(N_NODES + 7) / 8, 256>>>(We, att, cb, gam, bet, out, write_alpha);

    mma_final_kernel<<<mtiles, 256, SMEM>>>(bp, out);
}

// round 16
// speedup vs baseline: 1.0629x; 1.0629x over previous
#include <cuda_runtime.h>
#include <cuda_bf16.h>
#include <math.h>

#define N_NODES 50000
#define N_EDGES 800000
#define HID 256
#define IN_CH 320

typedef unsigned long long u64;
typedef unsigned int u32;

// ---------------- static scratch (no runtime allocation) ----------------
__device__ float4 g_posfeat4 [N_NODES * 64 / 4];     // (N,64) pos MLP output
__device__ float4 g_identity4[N_NODES * HID / 4];    // (N,256)
__device__ float4 g_xl4      [N_NODES * HID / 4];    // (N,256)
__device__ float4 g_xr4      [N_NODES * HID / 4];    // (N,256)
__device__ float4 g_outpre4  [N_NODES * HID / 4];    // (N,256)
__device__ float  g_norm_uv  [N_NODES * 2];
__device__ float4 g_logits4  [N_EDGES];              // (E,4) logits
__device__ int    g_deg      [N_NODES];
__device__ int    g_cursor   [N_NODES];
__device__ int    g_rowstart [N_NODES];
__device__ int2   g_csr      [N_EDGES];              // {eid, src}
__device__ int    g_blocksums[256];
__device__ int    g_ei_is64;

// bf16 hi/lo weights, transposed to [mat][n][k] for mma B operand
__device__ __align__(16) __nv_bfloat16 g_Bhi [3 * 256 * IN_CH];
__device__ __align__(16) __nv_bfloat16 g_Blo [3 * 256 * IN_CH];
__device__ __align__(16) __nv_bfloat16 g_Bphi[256 * 256];
__device__ __align__(16) __nv_bfloat16 g_Bplo[256 * 256];

#define g_posfeat  ((float*)g_posfeat4)
#define g_identity ((float*)g_identity4)
#define g_xl       ((float*)g_xl4)
#define g_xr       ((float*)g_xr4)
#define g_outpre   ((float*)g_outpre4)
#define g_logits   ((float*)g_logits4)

// ---------------- PTX helpers ----------------
__device__ __forceinline__ u32 smem_u32(const void* p) {
    u32 a;
    asm("{ .reg .u64 t; cvta.to.shared.u64 t, %1; cvt.u32.u64 %0, t; }"
        : "=r"(a) : "l"(p));
    return a;
}
__device__ __forceinline__ void ldmx4(u32* r, u32 a) {
    asm volatile("ldmatrix.sync.aligned.m8n8.x4.shared.b16 {%0,%1,%2,%3}, [%4];"
                 : "=r"(r[0]), "=r"(r[1]), "=r"(r[2]), "=r"(r[3]) : "r"(a));
}
__device__ __forceinline__ void mma16816(float* d, const u32* a, const u32* b) {
    asm volatile("mma.sync.aligned.m16n8k16.row.col.f32.bf16.bf16.f32 "
                 "{%0,%1,%2,%3}, {%4,%5,%6,%7}, {%8,%9}, {%0,%1,%2,%3};"
                 : "+f"(d[0]), "+f"(d[1]), "+f"(d[2]), "+f"(d[3])
                 : "r"(a[0]), "r"(a[1]), "r"(a[2]), "r"(a[3]),
                   "r"(b[0]), "r"(b[1]));
}

// ---------------- kernel: detect edge_index dtype (warp-parallel) -------
__global__ void detect_kernel(const int* __restrict__ ei32) {
    int lane = threadIdx.x & 31;
    int bad = 0;
    #pragma unroll
    for (int j = 0; j < 8; j++)
        if (ei32[2 * (lane * 8 + j) + 1] != 0) bad = 1;
    u32 m = __ballot_sync(0xffffffffu, bad);
    if (lane == 0) g_ei_is64 = (m == 0);
}
__device__ __forceinline__ int load_idx(const void* ei, long long pos) {
    if (g_ei_is64) return (int)((const long long*)ei)[pos];
    return ((const int*)ei)[pos];
}

// ---------------- kernel: zero CSR counters ----------------
__global__ void zero_csr_kernel() {
    int i = blockIdx.x * blockDim.x + threadIdx.x;
    if (i < N_NODES) { g_deg[i] = 0; g_cursor[i] = 0; }
}

// ---------------- kernel: weight convert: split-bf16, [mat][n][k] -------
__global__ void bconv_kernel(const float* __restrict__ Wres,
                             const float* __restrict__ Wl,
                             const float* __restrict__ Wr,
                             const float* __restrict__ Wp) {
    int i = blockIdx.x * blockDim.x + threadIdx.x;
    if (i < 3 * 256 * IN_CH) {
        int mat = i / (256 * IN_CH);
        int rem = i % (256 * IN_CH);
        int n = rem / IN_CH, k = rem % IN_CH;
        const float* W = (mat == 0) ? Wres : (mat == 1) ? Wl : Wr;
        float w = W[k * 256 + n];
        __nv_bfloat16 h = __float2bfloat16(w);
        g_Bhi[i] = h;
        g_Blo[i] = __float2bfloat16(w - __bfloat162float(h));
    }
    if (i < 256 * 256) {
        int n = i >> 8, k = i & 255;
        float w = Wp[k * 256 + n];
        __nv_bfloat16 h = __float2bfloat16(w);
        g_Bphi[i] = h;
        g_Bplo[i] = __float2bfloat16(w - __bfloat162float(h));
    }
}

// ---------------- kernel: node prep (norm_uv, pos-MLP) ----------------
__global__ void node_prep_kernel(const float* __restrict__ kpts,
                                 const float* __restrict__ pts3d,
                                 const float* __restrict__ W1,
                                 const float* __restrict__ b1,
                                 const float* __restrict__ W2,
                                 const float* __restrict__ b2) {
    __shared__ float sW1[96], sb1[32], sW2[2048], sb2[64];
    int t = threadIdx.x;
    for (int i = t; i < 96;   i += blockDim.x) sW1[i] = W1[i];
    for (int i = t; i < 32;   i += blockDim.x) sb1[i] = b1[i];
    for (int i = t; i < 2048; i += blockDim.x) sW2[i] = W2[i];
    for (int i = t; i < 64;   i += blockDim.x) sb2[i] = b2[i];
    __syncthreads();

    int tid = blockIdx.x * blockDim.x + t;
    int nth = gridDim.x * blockDim.x;

    for (int n = tid; n < N_NODES; n += nth) {
        float u   = kpts[n * 2]     / 1216.0f;
        float v   = kpts[n * 2 + 1] / 352.0f;
        float dep = pts3d[n * 3 + 2];
        g_norm_uv[n * 2]     = u;
        g_norm_uv[n * 2 + 1] = v;
        float h[32];
        #pragma unroll
        for (int j = 0; j < 32; j++) {
            float z = u * sW1[j] + v * sW1[32 + j] + dep * sW1[64 + j] + sb1[j];
            h[j] = z / (1.0f + __expf(-z));      // silu
        }
        float4* dst = (float4*)(g_posfeat + n * 64);
        #pragma unroll
        for (int j4 = 0; j4 < 16; j4++) {
            float o0 = sb2[j4 * 4 + 0], o1 = sb2[j4 * 4 + 1];
            float o2 = sb2[j4 * 4 + 2], o3 = sb2[j4 * 4 + 3];
            #pragma unroll
            for (int k = 0; k < 32; k++) {
                float hk = h[k];
                const float* w = sW2 + k * 64 + j4 * 4;
                o0 += hk * w[0]; o1 += hk * w[1];
                o2 += hk * w[2]; o3 += hk * w[3];
            }
            dst[j4] = make_float4(o0, o1, o2, o3);
        }
    }
}

// ---------------- kernels: CSR build (by dst) ----------------
__global__ void deg_kernel(const void* __restrict__ ei) {
    int e = blockIdx.x * blockDim.x + threadIdx.x;
    if (e >= N_EDGES) return;
    int d = load_idx(ei, (long long)N_EDGES + e);
    if (d >= 0 && d < N_NODES) atomicAdd(&g_deg[d], 1);
}

__global__ void scan_blocks_kernel() {
    int t = threadIdx.x, lane = t & 31, w = t >> 5;
    int i = blockIdx.x * 256 + t;
    int v = (i < N_NODES) ? g_deg[i] : 0;
    int x = v;
    #pragma unroll
    for (int off = 1; off < 32; off <<= 1) {
        int y = __shfl_up_sync(0xffffffffu, x, off);
        if (lane >= off) x += y;
    }
    __shared__ int wsum[8];
    if (lane == 31) wsum[w] = x;
    __syncthreads();
    if (w == 0) {
        int s = (lane < 8) ? wsum[lane] : 0;
        #pragma unroll
        for (int off = 1; off < 8; off <<= 1) {
            int y = __shfl_up_sync(0xffffffffu, s, off);
            if (lane >= off) s += y;
        }
        if (lane < 8) wsum[lane] = s;
    }
    __syncthreads();
    int incl = x + ((w > 0) ? wsum[w - 1] : 0);
    if (i < N_NODES) g_rowstart[i] = incl - v;       // block-local exclusive
    if (t == 255) g_blocksums[blockIdx.x] = incl;    // block total
}

__global__ void scan_sums_kernel(int nblocks) {
    int t = threadIdx.x, lane = t & 31, w = t >> 5;
    int v = (t < nblocks) ? g_blocksums[t] : 0;
    int x = v;
    #pragma unroll
    for (int off = 1; off < 32; off <<= 1) {
        int y = __shfl_up_sync(0xffffffffu, x, off);
        if (lane >= off) x += y;
    }
    __shared__ int wsum[8];
    if (lane == 31) wsum[w] = x;
    __syncthreads();
    if (w == 0) {
        int s = (lane < 8) ? wsum[lane] : 0;
        #pragma unroll
        for (int off = 1; off < 8; off <<= 1) {
            int y = __shfl_up_sync(0xffffffffu, s, off);
            if (lane >= off) s += y;
        }
        if (lane < 8) wsum[lane] = s;
    }
    __syncthreads();
    int incl = x + ((w > 0) ? wsum[w - 1] : 0);
    g_blocksums[t] = incl - v;                       // exclusive
}

__global__ void scan_add_kernel() {
    int i = blockIdx.x * 256 + threadIdx.x;
    if (i < N_NODES) g_rowstart[i] += g_blocksums[blockIdx.x];
}

__global__ void fill_kernel(const void* __restrict__ ei) {
    int e = blockIdx.x * blockDim.x + threadIdx.x;
    if (e >= N_EDGES) return;
    int d = load_idx(ei, (long long)N_EDGES + e);
    int s = load_idx(ei, e);
    if (d < 0 || d >= N_NODES) return;
    if (s < 0) s = 0; if (s >= N_NODES) s = N_NODES - 1;
    int p = atomicAdd(&g_cursor[d], 1);
    int idx = g_rowstart[d] + p;
    if (idx >= 0 && idx < N_EDGES) g_csr[idx] = make_int2(e, s);
}

// ---------------- split-bf16 3-pass HMMA GEMM (proven 128x128) ----------
template <int K>
__device__ __forceinline__ void mma_gemm_body(
    const float* __restrict__ A0, const float* __restrict__ A1,
    const __nv_bfloat16* __restrict__ Bh, const __nv_bfloat16* __restrict__ Bl,
    const float* __restrict__ bias, float* __restrict__ C,
    int cn, int bm)
{
    constexpr int NCHUNK = K / 16;
    extern __shared__ char smem[];
    u32 sb = smem_u32(smem);
    int t = threadIdx.x, lane = t & 31, wid = t >> 5;
    int wm = wid >> 1, wn = wid & 1;

    int lrow = t >> 1;
    int lko  = (t & 1) * 8;
    int gr   = bm + lrow;
    bool rok = gr < N_NODES;
    u32 st_off = (u32)lrow * 48 + (u32)(t & 1) * 16;

    float acc[2][8][4];
    #pragma unroll
    for (int i = 0; i < 2; i++)
        #pragma unroll
        for (int j = 0; j < 8; j++)
            #pragma unroll
            for (int q = 0; q < 4; q++) acc[i][j][q] = 0.0f;

    float v[8];
    uint4 vbh, vbl;

    auto ldg = [&](int kc) {
        int k0 = kc * 16;
        const float* p;
        if (K == 320 && k0 >= 256)
            p = A1 + (size_t)gr * 64 + (k0 - 256) + lko;
        else
            p = A0 + (size_t)gr * 256 + k0 + lko;
        if (rok) {
            float4 q0 = *(const float4*)p;
            float4 q1 = *(const float4*)(p + 4);
            v[0]=q0.x; v[1]=q0.y; v[2]=q0.z; v[3]=q0.w;
            v[4]=q1.x; v[5]=q1.y; v[6]=q1.z; v[7]=q1.w;
        } else {
            #pragma unroll
            for (int i = 0; i < 8; i++) v[i] = 0.0f;
        }
        size_t be = (size_t)(cn + lrow) * K + k0 + lko;
        vbh = *(const uint4*)(Bh + be);
        vbl = *(const uint4*)(Bl + be);
    };
    auto stsm = [&](int rb) {
        u32 h[4], l[4];
        #pragma unroll
        for (int j = 0; j < 4; j++) {
            __nv_bfloat162 hb = __floats2bfloat162_rn(v[2*j], v[2*j+1]);
            u32 hu = *(u32*)&hb;
            float f0 = __uint_as_float(hu << 16);
            float f1 = __uint_as_float(hu & 0xffff0000u);
            __nv_bfloat162 lb = __floats2bfloat162_rn(v[2*j] - f0, v[2*j+1] - f1);
            h[j] = hu; l[j] = *(u32*)&lb;
        }
        *(uint4*)(smem + rb +     0 + st_off) = make_uint4(h[0], h[1], h[2], h[3]);
        *(uint4*)(smem + rb +  6144 + st_off) = make_uint4(l[0], l[1], l[2], l[3]);
        *(uint4*)(smem + rb + 12288 + st_off) = vbh;
        *(uint4*)(smem + rb + 18432 + st_off) = vbl;
    };
    auto compute = [&](int rb) {
        u32 base = sb + rb;
        u32 ahi[2][4], alo[2][4];
        #pragma unroll
        for (int mi = 0; mi < 2; mi++) {
            u32 ra = base + (u32)(wm * 32 + mi * 16 + (lane & 15)) * 48
                          + (u32)(lane >> 4) * 16;
            ldmx4(ahi[mi], ra);
            ldmx4(alo[mi], ra + 6144);
        }
        #pragma unroll
        for (int np = 0; np < 4; np++) {
            int g  = lane >> 3;
            int nn = wn * 64 + np * 16 + ((g & 2) ? 8 : 0) + (lane & 7);
            u32 rb2 = base + 12288 + (u32)nn * 48 + (u32)(g & 1) * 16;
            u32 bh[4], bl2[4];
            ldmx4(bh, rb2);
            ldmx4(bl2, rb2 + 6144);
            #pragma unroll
            for (int mi = 0; mi < 2; mi++) {
                mma16816(acc[mi][np*2+0], ahi[mi], bh);
                mma16816(acc[mi][np*2+0], ahi[mi], bl2);
                mma16816(acc[mi][np*2+0], alo[mi], bh);
                mma16816(acc[mi][np*2+1], ahi[mi], bh + 2);
                mma16816(acc[mi][np*2+1], ahi[mi], bl2 + 2);
                mma16816(acc[mi][np*2+1], alo[mi], bh + 2);
            }
        }
    };

    ldg(0);
    stsm(0);
    __syncthreads();
    int buf = 0;
    for (int kc = 0; kc < NCHUNK; kc++) {
        bool more = (kc + 1) < NCHUNK;
        if (more) ldg(kc + 1);
        compute(buf * 24576);
        if (more) stsm((buf ^ 1) * 24576);
        __syncthreads();
        buf ^= 1;
    }

    #pragma unroll
    for (int mi = 0; mi < 2; mi++) {
        int row = bm + wm * 32 + mi * 16 + (lane >> 2);
        #pragma unroll
        for (int nj = 0; nj < 8; nj++) {
            int col = cn + wn * 64 + nj * 8 + 2 * (lane & 3);
            float b0 = bias[col], b1 = bias[col + 1];
            if (row < N_NODES)
                *(float2*)(C + (size_t)row * 256 + col) =
                    make_float2(acc[mi][nj][0] + b0, acc[mi][nj][1] + b1);
            if (row + 8 < N_NODES)
                *(float2*)(C + (size_t)(row + 8) * 256 + col) =
                    make_float2(acc[mi][nj][2] + b0, acc[mi][nj][3] + b1);
        }
    }
}

__global__ void __launch_bounds__(256)
mma_nodes_kernel(const float* __restrict__ x,
                 const float* __restrict__ bres,
                 const float* __restrict__ bl,
                 const float* __restrict__ br) {
    int y   = blockIdx.y;
    int mat = y >> 1;
    int cn  = (y & 1) * 128;
    const __nv_bfloat16* Bh = g_Bhi + (size_t)mat * 256 * IN_CH;
    const __nv_bfloat16* Bl = g_Blo + (size_t)mat * 256 * IN_CH;
    const float* bias = (mat == 0) ? bres : (mat == 1) ? bl : br;
    float* C          = (mat == 0) ? g_identity : (mat == 1) ? g_xl : g_xr;
    mma_gemm_body<IN_CH>(x, g_posfeat, Bh, Bl, bias, C, cn, blockIdx.x * 128);
}

__global__ void __launch_bounds__(256)
mma_final_kernel(const float* __restrict__ bp, float* __restrict__ out) {
    mma_gemm_body<HID>(g_outpre, nullptr, g_Bphi, g_Bplo, bp, out,
                       blockIdx.y * 128, blockIdx.x * 128);
}

// ---------------- attention: warp/node, depth-4 cp.async pipeline -------
__global__ void __launch_bounds__(256)
attn_kernel(const float* __restrict__ We,
            const float* __restrict__ att,
            const float* __restrict__ conv_bias,
            const float* __restrict__ gamma,
            const float* __restrict__ beta,
            float* __restrict__ out_final,
            int write_alpha) {
    __shared__ float sWe[768], sAtt[256], sCB[256], sG[256], sB[256];
    __shared__ __align__(16) float xlbuf[8][4][256];   // [warp][slot][ch]
    int t = threadIdx.x;
    for (int i = t; i < 768; i += 256) sWe[i] = We[i];
    sAtt[t] = att[t]; sCB[t] = conv_bias[t]; sG[t] = gamma[t]; sB[t] = beta[t];
    __syncthreads();

    int warp = t >> 5, lane = t & 31;
    int d = blockIdx.x * 8 + warp;
    if (d >= N_NODES) return;

    int c0 = lane * 8;
    int h  = lane >> 3;

    float xr[8], we0[8], we1[8], we2[8], ar[8];
    {
        const float4* p = (const float4*)(g_xr + (size_t)d * 256 + c0);
        float4 a = p[0], b = p[1];
        xr[0]=a.x; xr[1]=a.y; xr[2]=a.z; xr[3]=a.w;
        xr[4]=b.x; xr[5]=b.y; xr[6]=b.z; xr[7]=b.w;
    }
    #pragma unroll
    for (int i = 0; i < 8; i++) {
        we0[i] = sWe[c0 + i];
        we1[i] = sWe[256 + c0 + i];
        we2[i] = sWe[512 + c0 + i];
        ar[i]  = sAtt[c0 + i];
    }
    float uvd0 = g_norm_uv[d * 2], uvd1 = g_norm_uv[d * 2 + 1];
    int start = g_rowstart[d];
    int end   = start + g_deg[d];

    u32 bufaddr = smem_u32(&xlbuf[warp][0][0]) + (u32)c0 * 4;  // +slot*1024B

    float lm = -INFINITY, dn = 0.f;
    float acc[8] = {0,0,0,0,0,0,0,0};

    // issue edge q's gather into slot; ALWAYS commits a group (FIFO cadence)
    auto issue = [&](int q, int2& cj, float2& uvj, int slot) {
        if (q < end) {
            cj  = g_csr[q];
            uvj = *(const float2*)(g_norm_uv + (size_t)cj.y * 2);
            const float* sp = g_xl + (size_t)cj.y * 256 + c0;
            u32 dp = bufaddr + (u32)slot * 1024;
            asm volatile(
                "cp.async.ca.shared.global [%0], [%2], 16;\n\t"
                "cp.async.ca.shared.global [%1], [%3], 16;"
                :: "r"(dp), "r"(dp + 16), "l"(sp), "l"(sp + 4) : "memory");
        }
        asm volatile("cp.async.commit_group;" ::: "memory");
    };

    auto compute = [&](int2 cj, float2 uvj, int slot) {
        asm volatile("cp.async.wait_group 3;" ::: "memory");
        const float* bp_ = &xlbuf[warp][slot][c0];
        float4 ca = *(const float4*)bp_;
        float4 cb = *(const float4*)(bp_ + 4);
        float r0 = uvd0 - uvj.x;
        float r1 = uvd1 - uvj.y;
        float dist = sqrtf(r0 * r0 + r1 * r1);
        float xl[8] = {ca.x, ca.y, ca.z, ca.w, cb.x, cb.y, cb.z, cb.w};
        float part = 0.f;
        #pragma unroll
        for (int i = 0; i < 8; i++) {
            float m = xl[i] + xr[i] + r0 * we0[i] + r1 * we1[i] + dist * we2[i];
            m = (m >= 0.f) ? m : 0.2f * m;
            part += m * ar[i];
        }
        part += __shfl_xor_sync(0xffffffffu, part, 1);
        part += __shfl_xor_sync(0xffffffffu, part, 2);
        part += __shfl_xor_sync(0xffffffffu, part, 4);
        if ((lane & 7) == 0) g_logits[(size_t)cj.x * 4 + h] = part;

        float nm = fmaxf(lm, part);
        float sc = __expf(lm - nm);
        float ex = __expf(part - nm);
        dn = dn * sc + ex;
        #pragma unroll
        for (int i = 0; i < 8; i++) acc[i] = acc[i] * sc + ex * xl[i];
        lm = nm;
    };

    int2 e0, e1, e2, e3;
    float2 u0, u1, u2, u3;
    issue(start + 0, e0, u0, 0);
    issue(start + 1, e1, u1, 1);
    issue(start + 2, e2, u2, 2);
    issue(start + 3, e3, u3, 3);

    for (int p0 = start; p0 < end; p0 += 4) {
        if (p0 + 0 < end) { compute(e0, u0, 0); issue(p0 + 4, e0, u0, 0); }
        if (p0 + 1 < end) { compute(e1, u1, 1); issue(p0 + 5, e1, u1, 1); }
        if (p0 + 2 < end) { compute(e2, u2, 2); issue(p0 + 6, e2, u2, 2); }
        if (p0 + 3 < end) { compute(e3, u3, 3); issue(p0 + 7, e3, u3, 3); }
    }
    asm volatile("cp.async.wait_group 0;" ::: "memory");

    float dnT = dn + 1e-16f;

    if (write_alpha) {
        __threadfence_block();
        __syncwarp();
        float lmv[4], dnv[4];
        #pragma unroll
        for (int hh = 0; hh < 4; hh++) {
            lmv[hh] = __shfl_sync(0xffffffffu, lm,  hh * 8);
            dnv[hh] = __shfl_sync(0xffffffffu, dnT, hh * 8);
        }
        float* alpha_out = out_final + (size_t)N_NODES * 256;
        for (int q = start + lane; q < end; q += 32) {
            int eid = g_csr[q].x;
            float4 lg = g_logits4[eid];
            float4 al = make_float4(__expf(lg.x - lmv[0]) / dnv[0],
                                    __expf(lg.y - lmv[1]) / dnv[1],
                                    __expf(lg.z - lmv[2]) / dnv[2],
                                    __expf(lg.w - lmv[3]) / dnv[3]);
            *(float4*)(alpha_out + (size_t)eid * 4) = al;
        }
    }

    float o[8], s1 = 0.f, s2 = 0.f;
    float rdn = 1.0f / dnT;
    #pragma unroll
    for (int i = 0; i < 8; i++) {
        o[i] = acc[i] * rdn + sCB[c0 + i];
        s1 += o[i];
        s2 += o[i] * o[i];
    }
    #pragma unroll
    for (int off = 16; off >= 1; off >>= 1) {
        s1 += __shfl_xor_sync(0xffffffffu, s1, off);
        s2 += __shfl_xor_sync(0xffffffffu, s2, off);
    }
    float mean = s1 * (1.0f / 256.0f);
    float var  = s2 * (1.0f / 256.0f) - mean * mean;
    float rstd = rsqrtf(var + 1e-5f);

    const float4* ip = (const float4*)(g_identity + (size_t)d * 256 + c0);
    float4 ia = ip[0], ib = ip[1];
    float idn[8] = {ia.x, ia.y, ia.z, ia.w, ib.x, ib.y, ib.z, ib.w};

    float res[8];
    #pragma unroll
    for (int i = 0; i < 8; i++) {
        float y = (o[i] - mean) * rstd * sG[c0 + i] + sB[c0 + i];
        y = y / (1.0f + __expf(-y));
        res[i] = y + idn[i];
    }
    float4* op = (float4*)(g_outpre + (size_t)d * 256 + c0);
    op[0] = make_float4(res[0], res[1], res[2], res[3]);
    op[1] = make_float4(res[4], res[5], res[6], res[7]);
}

// ---------------- launch ----------------
extern "C" void kernel_launch(void* const* d_in, const int* in_sizes, int n_in,
                              void* d_out, int out_size) {
    const float* x    = (const float*)d_in[0];
    const float* kpts = (const float*)d_in[1];
    const float* p3d  = (const float*)d_in[2];
    const void*  ei   = d_in[3];
    const float* W1   = (const float*)d_in[4];
    const float* b1   = (const float*)d_in[5];
    const float* W2   = (const float*)d_in[6];
    const float* b2   = (const float*)d_in[7];
    const float* Wres = (const float*)d_in[8];
    const float* bres = (const float*)d_in[9];
    const float* Wl   = (const float*)d_in[10];
    const float* bl   = (const float*)d_in[11];
    const float* Wr   = (const float*)d_in[12];
    const float* br   = (const float*)d_in[13];
    const float* We   = (const float*)d_in[14];
    const float* att  = (const float*)d_in[15];
    const float* cb   = (const float*)d_in[16];
    const float* gam  = (const float*)d_in[17];
    const float* bet  = (const float*)d_in[18];
    const float* Wp   = (const float*)d_in[19];
    const float* bp   = (const float*)d_in[20];
    float* out = (float*)d_out;

    long long need = (long long)N_NODES * 256 + (long long)N_EDGES * 4;
    int write_alpha = ((long long)out_size >= need) ? 1 : 0;

    const int SMEM = 2 * 24576;   // 48KB double-buffered
    cudaFuncSetAttribute(mma_nodes_kernel,
                         cudaFuncAttributeMaxDynamicSharedMemorySize, SMEM);
    cudaFuncSetAttribute(mma_final_kernel,
                         cudaFuncAttributeMaxDynamicSharedMemorySize, SMEM);

    int mtiles = (N_NODES + 127) / 128;   // 391
    int nblk   = (N_NODES + 255) / 256;   // 196

    detect_kernel<<<1, 32>>>((const int*)ei);
    bconv_kernel<<<(3 * 256 * IN_CH + 255) / 256, 256>>>(Wres, Wl, Wr, Wp);
    node_prep_kernel<<<256, 256>>>(kpts, p3d, W1, b1, W2, b2);

    dim3 g1(mtiles, 6);
    mma_nodes_kernel<<<g1, 256, SMEM>>>(x, bres, bl, br);

    zero_csr_kernel<<<nblk, 256>>>();
    deg_kernel<<<(N_EDGES + 255) / 256, 256>>>(ei);
    scan_blocks_kernel<<<nblk, 256>>>();
    scan_sums_kernel<<<1, 256>>>(nblk);
    scan_add_kernel<<<nblk, 256>>>();
    fill_kernel<<<(N_EDGES + 255) / 256, 256>>>(ei);

    attn_kernel<<<(N_NODES + 7) / 8, 256>>>(We, att, cb, gam, bet, out, write_alpha);

    dim3 g2(mtiles, 2);
    mma_final_kernel<<<g2, 256, SMEM>>>(bp, out);
}

// round 17
// speedup vs baseline: 1.2756x; 1.2001x over previous
#include <cuda_runtime.h>
#include <cuda_bf16.h>
#include <math.h>

#define N_NODES 50000
#define N_EDGES 800000
#define HID 256
#define KX 288            // composed GEMM depth: 256 (x) + 32 (h)

typedef unsigned long long u64;
typedef unsigned int u32;

// ---------------- static scratch (no runtime allocation) ----------------
__device__ float4 g_hfeat4   [N_NODES * 32 / 4];     // (N,32) silu(pos@W1+b1)
__device__ float4 g_identity4[N_NODES * HID / 4];    // (N,256)
__device__ float4 g_xl4      [N_NODES * HID / 4];    // (N,256)
__device__ float4 g_xr4      [N_NODES * HID / 4];    // (N,256)
__device__ float4 g_outpre4  [N_NODES * HID / 4];    // (N,256)
__device__ float  g_norm_uv  [N_NODES * 2];
__device__ float4 g_logits4  [N_EDGES];              // (E,4) logits
__device__ int    g_deg      [N_NODES];
__device__ int    g_cursor   [N_NODES];
__device__ int    g_rowstart [N_NODES];
__device__ int2   g_csr      [N_EDGES];              // {eid, src}
__device__ int    g_blocksums[256];
__device__ int    g_ei_is64;
__device__ float  g_bias2    [3 * 256];              // composed biases

// bf16 hi/lo composed weights, [mat][n][k], K=288
__device__ __align__(16) __nv_bfloat16 g_Bhi [3 * 256 * KX];
__device__ __align__(16) __nv_bfloat16 g_Blo [3 * 256 * KX];
__device__ __align__(16) __nv_bfloat16 g_Bphi[256 * 256];
__device__ __align__(16) __nv_bfloat16 g_Bplo[256 * 256];

#define g_hfeat    ((float*)g_hfeat4)
#define g_identity ((float*)g_identity4)
#define g_xl       ((float*)g_xl4)
#define g_xr       ((float*)g_xr4)
#define g_outpre   ((float*)g_outpre4)
#define g_logits   ((float*)g_logits4)

// ---------------- PTX helpers ----------------
__device__ __forceinline__ u32 smem_u32(const void* p) {
    u32 a;
    asm("{ .reg .u64 t; cvta.to.shared.u64 t, %1; cvt.u32.u64 %0, t; }"
        : "=r"(a) : "l"(p));
    return a;
}
__device__ __forceinline__ void ldmx4(u32* r, u32 a) {
    asm volatile("ldmatrix.sync.aligned.m8n8.x4.shared.b16 {%0,%1,%2,%3}, [%4];"
                 : "=r"(r[0]), "=r"(r[1]), "=r"(r[2]), "=r"(r[3]) : "r"(a));
}
__device__ __forceinline__ void mma16816(float* d, const u32* a, const u32* b) {
    asm volatile("mma.sync.aligned.m16n8k16.row.col.f32.bf16.bf16.f32 "
                 "{%0,%1,%2,%3}, {%4,%5,%6,%7}, {%8,%9}, {%0,%1,%2,%3};"
                 : "+f"(d[0]), "+f"(d[1]), "+f"(d[2]), "+f"(d[3])
                 : "r"(a[0]), "r"(a[1]), "r"(a[2]), "r"(a[3]),
                   "r"(b[0]), "r"(b[1]));
}

// ---------------- kernel: detect edge_index dtype (warp-parallel) -------
__global__ void detect_kernel(const int* __restrict__ ei32) {
    int lane = threadIdx.x & 31;
    int bad = 0;
    #pragma unroll
    for (int j = 0; j < 8; j++)
        if (ei32[2 * (lane * 8 + j) + 1] != 0) bad = 1;
    u32 m = __ballot_sync(0xffffffffu, bad);
    if (lane == 0) g_ei_is64 = (m == 0);
}
__device__ __forceinline__ int load_idx(const void* ei, long long pos) {
    if (g_ei_is64) return (int)((const long long*)ei)[pos];
    return ((const int*)ei)[pos];
}

// ---------------- kernel: zero CSR counters ----------------
__global__ void zero_csr_kernel() {
    int i = blockIdx.x * blockDim.x + threadIdx.x;
    if (i < N_NODES) { g_deg[i] = 0; g_cursor[i] = 0; }
}

// ---------------- kernel: weight compose + split-bf16 convert -----------
// For k<256: composed W row = W[k]; for k>=256: W2[k-256] @ W[256:320].
// Bias: b' = b + b2 @ W[256:320]. Also converts Wp (unchanged).
__global__ void bconv_kernel(const float* __restrict__ W2,
                             const float* __restrict__ b2,
                             const float* __restrict__ Wres,
                             const float* __restrict__ bres,
                             const float* __restrict__ Wl,
                             const float* __restrict__ bl,
                             const float* __restrict__ Wr,
                             const float* __restrict__ br,
                             const float* __restrict__ Wp) {
    int i = blockIdx.x * blockDim.x + threadIdx.x;
    if (i < 3 * 256 * KX) {
        int mat = i / (256 * KX);
        int rem = i % (256 * KX);
        int n = rem / KX, k = rem % KX;
        const float* W = (mat == 0) ? Wres : (mat == 1) ? Wl : Wr;
        float w;
        if (k < 256) {
            w = W[k * 256 + n];
        } else {
            const float* w2 = W2 + (k - 256) * 64;
            float s = 0.f;
            #pragma unroll 8
            for (int j = 0; j < 64; j++)
                s += w2[j] * W[(256 + j) * 256 + n];
            w = s;
        }
        __nv_bfloat16 h = __float2bfloat16(w);
        g_Bhi[i] = h;
        g_Blo[i] = __float2bfloat16(w - __bfloat162float(h));
    }
    if (i < 256 * 256) {
        int n = i >> 8, k = i & 255;
        float w = Wp[k * 256 + n];
        __nv_bfloat16 h = __float2bfloat16(w);
        g_Bphi[i] = h;
        g_Bplo[i] = __float2bfloat16(w - __bfloat162float(h));
    }
    if (i < 3 * 256) {
        int mat = i >> 8, n = i & 255;
        const float* W  = (mat == 0) ? Wres : (mat == 1) ? Wl : Wr;
        const float* bb = (mat == 0) ? bres : (mat == 1) ? bl : br;
        float s = bb[n];
        #pragma unroll 8
        for (int j = 0; j < 64; j++)
            s += b2[j] * W[(256 + j) * 256 + n];
        g_bias2[i] = s;
    }
}

// ---------------- kernel: node prep (norm_uv + h only) ----------------
__global__ void node_prep_kernel(const float* __restrict__ kpts,
                                 const float* __restrict__ pts3d,
                                 const float* __restrict__ W1,
                                 const float* __restrict__ b1) {
    __shared__ float sW1[96], sb1[32];
    int t = threadIdx.x;
    for (int i = t; i < 96; i += blockDim.x) sW1[i] = W1[i];
    for (int i = t; i < 32; i += blockDim.x) sb1[i] = b1[i];
    __syncthreads();

    int tid = blockIdx.x * blockDim.x + t;
    int nth = gridDim.x * blockDim.x;

    for (int n = tid; n < N_NODES; n += nth) {
        float u   = kpts[n * 2]     / 1216.0f;
        float v   = kpts[n * 2 + 1] / 352.0f;
        float dep = pts3d[n * 3 + 2];
        g_norm_uv[n * 2]     = u;
        g_norm_uv[n * 2 + 1] = v;
        float4* dst = (float4*)(g_hfeat + n * 32);
        #pragma unroll
        for (int j4 = 0; j4 < 8; j4++) {
            float hh[4];
            #pragma unroll
            for (int q = 0; q < 4; q++) {
                int j = j4 * 4 + q;
                float z = u * sW1[j] + v * sW1[32 + j] + dep * sW1[64 + j] + sb1[j];
                hh[q] = z / (1.0f + __expf(-z));   // silu
            }
            dst[j4] = make_float4(hh[0], hh[1], hh[2], hh[3]);
        }
    }
}

// ---------------- kernels: CSR build (by dst) ----------------
__global__ void deg_kernel(const void* __restrict__ ei) {
    int e = blockIdx.x * blockDim.x + threadIdx.x;
    if (e >= N_EDGES) return;
    int d = load_idx(ei, (long long)N_EDGES + e);
    if (d >= 0 && d < N_NODES) atomicAdd(&g_deg[d], 1);
}

__global__ void scan_blocks_kernel() {
    int t = threadIdx.x, lane = t & 31, w = t >> 5;
    int i = blockIdx.x * 256 + t;
    int v = (i < N_NODES) ? g_deg[i] : 0;
    int x = v;
    #pragma unroll
    for (int off = 1; off < 32; off <<= 1) {
        int y = __shfl_up_sync(0xffffffffu, x, off);
        if (lane >= off) x += y;
    }
    __shared__ int wsum[8];
    if (lane == 31) wsum[w] = x;
    __syncthreads();
    if (w == 0) {
        int s = (lane < 8) ? wsum[lane] : 0;
        #pragma unroll
        for (int off = 1; off < 8; off <<= 1) {
            int y = __shfl_up_sync(0xffffffffu, s, off);
            if (lane >= off) s += y;
        }
        if (lane < 8) wsum[lane] = s;
    }
    __syncthreads();
    int incl = x + ((w > 0) ? wsum[w - 1] : 0);
    if (i < N_NODES) g_rowstart[i] = incl - v;
    if (t == 255) g_blocksums[blockIdx.x] = incl;
}

__global__ void scan_sums_kernel(int nblocks) {
    int t = threadIdx.x, lane = t & 31, w = t >> 5;
    int v = (t < nblocks) ? g_blocksums[t] : 0;
    int x = v;
    #pragma unroll
    for (int off = 1; off < 32; off <<= 1) {
        int y = __shfl_up_sync(0xffffffffu, x, off);
        if (lane >= off) x += y;
    }
    __shared__ int wsum[8];
    if (lane == 31) wsum[w] = x;
    __syncthreads();
    if (w == 0) {
        int s = (lane < 8) ? wsum[lane] : 0;
        #pragma unroll
        for (int off = 1; off < 8; off <<= 1) {
            int y = __shfl_up_sync(0xffffffffu, s, off);
            if (lane >= off) s += y;
        }
        if (lane < 8) wsum[lane] = s;
    }
    __syncthreads();
    int incl = x + ((w > 0) ? wsum[w - 1] : 0);
    g_blocksums[t] = incl - v;
}

__global__ void scan_add_kernel() {
    int i = blockIdx.x * 256 + threadIdx.x;
    if (i < N_NODES) g_rowstart[i] += g_blocksums[blockIdx.x];
}

__global__ void fill_kernel(const void* __restrict__ ei) {
    int e = blockIdx.x * blockDim.x + threadIdx.x;
    if (e >= N_EDGES) return;
    int d = load_idx(ei, (long long)N_EDGES + e);
    int s = load_idx(ei, e);
    if (d < 0 || d >= N_NODES) return;
    if (s < 0) s = 0; if (s >= N_NODES) s = N_NODES - 1;
    int p = atomicAdd(&g_cursor[d], 1);
    int idx = g_rowstart[d] + p;
    if (idx >= 0 && idx < N_EDGES) g_csr[idx] = make_int2(e, s);
}

// ---------------- split-bf16 3-pass HMMA GEMM (proven 128x128) ----------
// K=288: k<256 from A0 (stride 256), k>=256 from A1=h (stride 32).
template <int K>
__device__ __forceinline__ void mma_gemm_body(
    const float* __restrict__ A0, const float* __restrict__ A1,
    const __nv_bfloat16* __restrict__ Bh, const __nv_bfloat16* __restrict__ Bl,
    const float* __restrict__ bias, float* __restrict__ C,
    int cn, int bm)
{
    constexpr int NCHUNK = K / 16;
    extern __shared__ char smem[];
    u32 sb = smem_u32(smem);
    int t = threadIdx.x, lane = t & 31, wid = t >> 5;
    int wm = wid >> 1, wn = wid & 1;

    int lrow = t >> 1;
    int lko  = (t & 1) * 8;
    int gr   = bm + lrow;
    bool rok = gr < N_NODES;
    u32 st_off = (u32)lrow * 48 + (u32)(t & 1) * 16;

    float acc[2][8][4];
    #pragma unroll
    for (int i = 0; i < 2; i++)
        #pragma unroll
        for (int j = 0; j < 8; j++)
            #pragma unroll
            for (int q = 0; q < 4; q++) acc[i][j][q] = 0.0f;

    float v[8];
    uint4 vbh, vbl;

    auto ldg = [&](int kc) {
        int k0 = kc * 16;
        const float* p;
        if (K == KX && k0 >= 256)
            p = A1 + (size_t)gr * 32 + (k0 - 256) + lko;
        else
            p = A0 + (size_t)gr * 256 + k0 + lko;
        if (rok) {
            float4 q0 = *(const float4*)p;
            float4 q1 = *(const float4*)(p + 4);
            v[0]=q0.x; v[1]=q0.y; v[2]=q0.z; v[3]=q0.w;
            v[4]=q1.x; v[5]=q1.y; v[6]=q1.z; v[7]=q1.w;
        } else {
            #pragma unroll
            for (int i = 0; i < 8; i++) v[i] = 0.0f;
        }
        size_t be = (size_t)(cn + lrow) * K + k0 + lko;
        vbh = *(const uint4*)(Bh + be);
        vbl = *(const uint4*)(Bl + be);
    };
    auto stsm = [&](int rb) {
        u32 h[4], l[4];
        #pragma unroll
        for (int j = 0; j < 4; j++) {
            __nv_bfloat162 hb = __floats2bfloat162_rn(v[2*j], v[2*j+1]);
            u32 hu = *(u32*)&hb;
            float f0 = __uint_as_float(hu << 16);
            float f1 = __uint_as_float(hu & 0xffff0000u);
            __nv_bfloat162 lb = __floats2bfloat162_rn(v[2*j] - f0, v[2*j+1] - f1);
            h[j] = hu; l[j] = *(u32*)&lb;
        }
        *(uint4*)(smem + rb +     0 + st_off) = make_uint4(h[0], h[1], h[2], h[3]);
        *(uint4*)(smem + rb +  6144 + st_off) = make_uint4(l[0], l[1], l[2], l[3]);
        *(uint4*)(smem + rb + 12288 + st_off) = vbh;
        *(uint4*)(smem + rb + 18432 + st_off) = vbl;
    };
    auto compute = [&](int rb) {
        u32 base = sb + rb;
        u32 ahi[2][4], alo[2][4];
        #pragma unroll
        for (int mi = 0; mi < 2; mi++) {
            u32 ra = base + (u32)(wm * 32 + mi * 16 + (lane & 15)) * 48
                          + (u32)(lane >> 4) * 16;
            ldmx4(ahi[mi], ra);
            ldmx4(alo[mi], ra + 6144);
        }
        #pragma unroll
        for (int np = 0; np < 4; np++) {
            int g  = lane >> 3;
            int nn = wn * 64 + np * 16 + ((g & 2) ? 8 : 0) + (lane & 7);
            u32 rb2 = base + 12288 + (u32)nn * 48 + (u32)(g & 1) * 16;
            u32 bh[4], bl2[4];
            ldmx4(bh, rb2);
            ldmx4(bl2, rb2 + 6144);
            #pragma unroll
            for (int mi = 0; mi < 2; mi++) {
                mma16816(acc[mi][np*2+0], ahi[mi], bh);
                mma16816(acc[mi][np*2+0], ahi[mi], bl2);
                mma16816(acc[mi][np*2+0], alo[mi], bh);
                mma16816(acc[mi][np*2+1], ahi[mi], bh + 2);
                mma16816(acc[mi][np*2+1], ahi[mi], bl2 + 2);
                mma16816(acc[mi][np*2+1], alo[mi], bh + 2);
            }
        }
    };

    ldg(0);
    stsm(0);
    __syncthreads();
    int buf = 0;
    for (int kc = 0; kc < NCHUNK; kc++) {
        bool more = (kc + 1) < NCHUNK;
        if (more) ldg(kc + 1);
        compute(buf * 24576);
        if (more) stsm((buf ^ 1) * 24576);
        __syncthreads();
        buf ^= 1;
    }

    #pragma unroll
    for (int mi = 0; mi < 2; mi++) {
        int row = bm + wm * 32 + mi * 16 + (lane >> 2);
        #pragma unroll
        for (int nj = 0; nj < 8; nj++) {
            int col = cn + wn * 64 + nj * 8 + 2 * (lane & 3);
            float b0 = bias[col], b1 = bias[col + 1];
            if (row < N_NODES)
                *(float2*)(C + (size_t)row * 256 + col) =
                    make_float2(acc[mi][nj][0] + b0, acc[mi][nj][1] + b1);
            if (row + 8 < N_NODES)
                *(float2*)(C + (size_t)(row + 8) * 256 + col) =
                    make_float2(acc[mi][nj][2] + b0, acc[mi][nj][3] + b1);
        }
    }
}

__global__ void __launch_bounds__(256)
mma_nodes_kernel(const float* __restrict__ x) {
    int y   = blockIdx.y;
    int mat = y >> 1;
    int cn  = (y & 1) * 128;
    const __nv_bfloat16* Bh = g_Bhi + (size_t)mat * 256 * KX;
    const __nv_bfloat16* Bl = g_Blo + (size_t)mat * 256 * KX;
    const float* bias = g_bias2 + mat * 256;
    float* C = (mat == 0) ? g_identity : (mat == 1) ? g_xl : g_xr;
    mma_gemm_body<KX>(x, g_hfeat, Bh, Bl, bias, C, cn, blockIdx.x * 128);
}

__global__ void __launch_bounds__(256)
mma_final_kernel(const float* __restrict__ bp, float* __restrict__ out) {
    mma_gemm_body<HID>(g_outpre, nullptr, g_Bphi, g_Bplo, bp, out,
                       blockIdx.y * 128, blockIdx.x * 128);
}

// ---------------- attention: warp/node, depth-4 cp.async pipeline -------
__global__ void __launch_bounds__(256)
attn_kernel(const float* __restrict__ We,
            const float* __restrict__ att,
            const float* __restrict__ conv_bias,
            const float* __restrict__ gamma,
            const float* __restrict__ beta,
            float* __restrict__ out_final,
            int write_alpha) {
    __shared__ float sWe[768], sAtt[256], sCB[256], sG[256], sB[256];
    __shared__ __align__(16) float xlbuf[8][4][256];   // [warp][slot][ch]
    int t = threadIdx.x;
    for (int i = t; i < 768; i += 256) sWe[i] = We[i];
    sAtt[t] = att[t]; sCB[t] = conv_bias[t]; sG[t] = gamma[t]; sB[t] = beta[t];
    __syncthreads();

    int warp = t >> 5, lane = t & 31;
    int d = blockIdx.x * 8 + warp;
    if (d >= N_NODES) return;

    int c0 = lane * 8;
    int h  = lane >> 3;

    float xr[8], we0[8], we1[8], we2[8], ar[8];
    {
        const float4* p = (const float4*)(g_xr + (size_t)d * 256 + c0);
        float4 a = p[0], b = p[1];
        xr[0]=a.x; xr[1]=a.y; xr[2]=a.z; xr[3]=a.w;
        xr[4]=b.x; xr[5]=b.y; xr[6]=b.z; xr[7]=b.w;
    }
    #pragma unroll
    for (int i = 0; i < 8; i++) {
        we0[i] = sWe[c0 + i];
        we1[i] = sWe[256 + c0 + i];
        we2[i] = sWe[512 + c0 + i];
        ar[i]  = sAtt[c0 + i];
    }
    float uvd0 = g_norm_uv[d * 2], uvd1 = g_norm_uv[d * 2 + 1];
    int start = g_rowstart[d];
    int end   = start + g_deg[d];

    u32 bufaddr = smem_u32(&xlbuf[warp][0][0]) + (u32)c0 * 4;  // +slot*1024B

    float lm = -INFINITY, dn = 0.f;
    float acc[8] = {0,0,0,0,0,0,0,0};

    auto issue = [&](int q, int2& cj, float2& uvj, int slot) {
        if (q < end) {
            cj  = g_csr[q];
            uvj = *(const float2*)(g_norm_uv + (size_t)cj.y * 2);
            const float* sp = g_xl + (size_t)cj.y * 256 + c0;
            u32 dp = bufaddr + (u32)slot * 1024;
            asm volatile(
                "cp.async.ca.shared.global [%0], [%2], 16;\n\t"
                "cp.async.ca.shared.global [%1], [%3], 16;"
                :: "r"(dp), "r"(dp + 16), "l"(sp), "l"(sp + 4) : "memory");
        }
        asm volatile("cp.async.commit_group;" ::: "memory");
    };

    auto compute = [&](int2 cj, float2 uvj, int slot) {
        asm volatile("cp.async.wait_group 3;" ::: "memory");
        const float* bp_ = &xlbuf[warp][slot][c0];
        float4 ca = *(const float4*)bp_;
        float4 cb = *(const float4*)(bp_ + 4);
        float r0 = uvd0 - uvj.x;
        float r1 = uvd1 - uvj.y;
        float dist = sqrtf(r0 * r0 + r1 * r1);
        float xl[8] = {ca.x, ca.y, ca.z, ca.w, cb.x, cb.y, cb.z, cb.w};
        float part = 0.f;
        #pragma unroll
        for (int i = 0; i < 8; i++) {
            float m = xl[i] + xr[i] + r0 * we0[i] + r1 * we1[i] + dist * we2[i];
            m = (m >= 0.f) ? m : 0.2f * m;
            part += m * ar[i];
        }
        part += __shfl_xor_sync(0xffffffffu, part, 1);
        part += __shfl_xor_sync(0xffffffffu, part, 2);
        part += __shfl_xor_sync(0xffffffffu, part, 4);
        if ((lane & 7) == 0) g_logits[(size_t)cj.x * 4 + h] = part;

        float nm = fmaxf(lm, part);
        float sc = __expf(lm - nm);
        float ex = __expf(part - nm);
        dn = dn * sc + ex;
        #pragma unroll
        for (int i = 0; i < 8; i++) acc[i] = acc[i] * sc + ex * xl[i];
        lm = nm;
    };

    int2 e0, e1, e2, e3;
    float2 u0, u1, u2, u3;
    issue(start + 0, e0, u0, 0);
    issue(start + 1, e1, u1, 1);
    issue(start + 2, e2, u2, 2);
    issue(start + 3, e3, u3, 3);

    for (int p0 = start; p0 < end; p0 += 4) {
        if (p0 + 0 < end) { compute(e0, u0, 0); issue(p0 + 4, e0, u0, 0); }
        if (p0 + 1 < end) { compute(e1, u1, 1); issue(p0 + 5, e1, u1, 1); }
        if (p0 + 2 < end) { compute(e2, u2, 2); issue(p0 + 6, e2, u2, 2); }
        if (p0 + 3 < end) { compute(e3, u3, 3); issue(p0 + 7, e3, u3, 3); }
    }
    asm volatile("cp.async.wait_group 0;" ::: "memory");

    float dnT = dn + 1e-16f;

    if (write_alpha) {
        __threadfence_block();
        __syncwarp();
        float lmv[4], dnv[4];
        #pragma unroll
        for (int hh = 0; hh < 4; hh++) {
            lmv[hh] = __shfl_sync(0xffffffffu, lm,  hh * 8);
            dnv[hh] = __shfl_sync(0xffffffffu, dnT, hh * 8);
        }
        float* alpha_out = out_final + (size_t)N_NODES * 256;
        for (int q = start + lane; q < end; q += 32) {
            int eid = g_csr[q].x;
            float4 lg = g_logits4[eid];
            float4 al = make_float4(__expf(lg.x - lmv[0]) / dnv[0],
                                    __expf(lg.y - lmv[1]) / dnv[1],
                                    __expf(lg.z - lmv[2]) / dnv[2],
                                    __expf(lg.w - lmv[3]) / dnv[3]);
            *(float4*)(alpha_out + (size_t)eid * 4) = al;
        }
    }

    float o[8], s1 = 0.f, s2 = 0.f;
    float rdn = 1.0f / dnT;
    #pragma unroll
    for (int i = 0; i < 8; i++) {
        o[i] = acc[i] * rdn + sCB[c0 + i];
        s1 += o[i];
        s2 += o[i] * o[i];
    }
    #pragma unroll
    for (int off = 16; off >= 1; off >>= 1) {
        s1 += __shfl_xor_sync(0xffffffffu, s1, off);
        s2 += __shfl_xor_sync(0xffffffffu, s2, off);
    }
    float mean = s1 * (1.0f / 256.0f);
    float var  = s2 * (1.0f / 256.0f) - mean * mean;
    float rstd = rsqrtf(var + 1e-5f);

    const float4* ip = (const float4*)(g_identity + (size_t)d * 256 + c0);
    float4 ia = ip[0], ib = ip[1];
    float idn[8] = {ia.x, ia.y, ia.z, ia.w, ib.x, ib.y, ib.z, ib.w};

    float res[8];
    #pragma unroll
    for (int i = 0; i < 8; i++) {
        float y = (o[i] - mean) * rstd * sG[c0 + i] + sB[c0 + i];
        y = y / (1.0f + __expf(-y));
        res[i] = y + idn[i];
    }
    float4* op = (float4*)(g_outpre + (size_t)d * 256 + c0);
    op[0] = make_float4(res[0], res[1], res[2], res[3]);
    op[1] = make_float4(res[4], res[5], res[6], res[7]);
}

// ---------------- launch ----------------
extern "C" void kernel_launch(void* const* d_in, const int* in_sizes, int n_in,
                              void* d_out, int out_size) {
    const float* x    = (const float*)d_in[0];
    const float* kpts = (const float*)d_in[1];
    const float* p3d  = (const float*)d_in[2];
    const void*  ei   = d_in[3];
    const float* W1   = (const float*)d_in[4];
    const float* b1   = (const float*)d_in[5];
    const float* W2   = (const float*)d_in[6];
    const float* b2   = (const float*)d_in[7];
    const float* Wres = (const float*)d_in[8];
    const float* bres = (const float*)d_in[9];
    const float* Wl   = (const float*)d_in[10];
    const float* bl   = (const float*)d_in[11];
    const float* Wr   = (const float*)d_in[12];
    const float* br   = (const float*)d_in[13];
    const float* We   = (const float*)d_in[14];
    const float* att  = (const float*)d_in[15];
    const float* cb   = (const float*)d_in[16];
    const float* gam  = (const float*)d_in[17];
    const float* bet  = (const float*)d_in[18];
    const float* Wp   = (const float*)d_in[19];
    const float* bp   = (const float*)d_in[20];
    float* out = (float*)d_out;

    long long need = (long long)N_NODES * 256 + (long long)N_EDGES * 4;
    int write_alpha = ((long long)out_size >= need) ? 1 : 0;

    const int SMEM = 2 * 24576;   // 48KB double-buffered
    cudaFuncSetAttribute(mma_nodes_kernel,
                         cudaFuncAttributeMaxDynamicSharedMemorySize, SMEM);
    cudaFuncSetAttribute(mma_final_kernel,
                         cudaFuncAttributeMaxDynamicSharedMemorySize, SMEM);

    int mtiles = (N_NODES + 127) / 128;   // 391
    int nblk   = (N_NODES + 255) / 256;   // 196

    detect_kernel<<<1, 32>>>((const int*)ei);
    bconv_kernel<<<(3 * 256 * KX + 255) / 256, 256>>>(
        W2, b2, Wres, bres, Wl, bl, Wr, br, Wp);
    node_prep_kernel<<<256, 256>>>(kpts, p3d, W1, b1);

    dim3 g1(mtiles, 6);
    mma_nodes_kernel<<<g1, 256, SMEM>>>(x);

    zero_csr_kernel<<<nblk, 256>>>();
    deg_kernel<<<(N_EDGES + 255) / 256, 256>>>(ei);
    scan_blocks_kernel<<<nblk, 256>>>();
    scan_sums_kernel<<<1, 256>>>(nblk);
    scan_add_kernel<<<nblk, 256>>>();
    fill_kernel<<<(N_EDGES + 255) / 256, 256>>>(ei);

    attn_kernel<<<(N_NODES + 7) / 8, 256>>>(We, att, cb, gam, bet, out, write_alpha);

    dim3 g2(mtiles, 2);
    mma_final_kernel<<<g2, 256, SMEM>>>(bp, out);
}